// round 1
// baseline (speedup 1.0000x reference)
#include <cuda_runtime.h>
#include <cstddef>

#define N_NODES 50000
#define N_EDGES 500000
#define HID 128
#define NREL 4
#define BN_EPS 1e-5f

// ---------------- scratch (static device globals; no cudaMalloc allowed) ----
__device__ int   g_cnt[NREL * N_NODES];
__device__ int   g_cursor[NREL * N_NODES];
__device__ float g_dinv[NREL * N_NODES];
__device__ int   g_rowptr[NREL * (N_NODES + 1)];
__device__ int   g_col[NREL * N_EDGES];
__device__ float g_agg[(size_t)NREL * N_NODES * HID];   // 102.4 MB
__device__ float g_h1[(size_t)N_NODES * HID];
__device__ float g_h2[(size_t)N_NODES * HID];
__device__ float g_h3[(size_t)N_NODES * HID];
__device__ float g_bnsum[HID];
__device__ float g_bnsq[HID];
__device__ float g_Wp[HID * HID];
__device__ float g_bp[HID];

// ---------------- init ------------------------------------------------------
__global__ void init_kernel() {
    int i = blockIdx.x * blockDim.x + threadIdx.x;
    if (i < NREL * N_NODES) { g_cnt[i] = 0; g_cursor[i] = 0; }
    if (i < HID) { g_bnsum[i] = 0.f; g_bnsq[i] = 0.f; }
}

// ---------------- degree count ----------------------------------------------
__global__ void count_kernel(const int* __restrict__ ei) {
    int r = blockIdx.y;
    int e = blockIdx.x * blockDim.x + threadIdx.x;
    if (e >= N_EDGES) return;
    int dst = ei[((size_t)r * 2 + 1) * N_EDGES + e];
    atomicAdd(&g_cnt[r * N_NODES + dst], 1);
}

// ---------------- dinv = rsqrt(deg_edges + 1 selfloop) -----------------------
__global__ void dinv_kernel() {
    int i = blockIdx.x * blockDim.x + threadIdx.x;
    if (i >= NREL * N_NODES) return;
    g_dinv[i] = rsqrtf((float)g_cnt[i] + 1.0f);
}

// ---------------- exclusive scan -> rowptr (1 block per relation) ------------
__global__ void scan_kernel() {
    int r = blockIdx.x;
    int tid = threadIdx.x;
    __shared__ int s[1024];
    __shared__ int offset;
    if (tid == 0) { offset = 0; g_rowptr[r * (N_NODES + 1)] = 0; }
    __syncthreads();
    for (int base = 0; base < N_NODES; base += 1024) {
        int i = base + tid;
        int v = (i < N_NODES) ? g_cnt[r * N_NODES + i] : 0;
        s[tid] = v;
        #pragma unroll
        for (int d = 1; d < 1024; d <<= 1) {
            __syncthreads();
            int t = (tid >= d) ? s[tid - d] : 0;
            __syncthreads();
            s[tid] += t;
        }
        __syncthreads();
        if (i < N_NODES) g_rowptr[r * (N_NODES + 1) + i + 1] = offset + s[tid];
        __syncthreads();
        if (tid == 0) offset += s[1023];
        __syncthreads();
    }
}

// ---------------- fill CSR ---------------------------------------------------
__global__ void fill_kernel(const int* __restrict__ ei) {
    int r = blockIdx.y;
    int e = blockIdx.x * blockDim.x + threadIdx.x;
    if (e >= N_EDGES) return;
    int src = ei[(size_t)r * 2 * N_EDGES + e];
    int dst = ei[((size_t)r * 2 + 1) * N_EDGES + e];
    int pos = g_rowptr[r * (N_NODES + 1) + dst] + atomicAdd(&g_cursor[r * N_NODES + dst], 1);
    g_col[(size_t)r * N_EDGES + pos] = src;
}

// ---------------- CSR aggregate: agg[r][n] = dinv_n*(dinv_n*x_n + sum dinv_s*x_s)
__global__ void aggregate_kernel(const float* __restrict__ X) {
    int r = blockIdx.y;
    int node = blockIdx.x * 8 + (threadIdx.x >> 5);
    if (node >= N_NODES) return;
    int lane = threadIdx.x & 31;
    const float4* x4 = (const float4*)X;
    float dd = g_dinv[r * N_NODES + node];
    float4 xv = x4[(size_t)node * 32 + lane];
    float4 acc;
    acc.x = dd * xv.x; acc.y = dd * xv.y; acc.z = dd * xv.z; acc.w = dd * xv.w;
    int beg = g_rowptr[r * (N_NODES + 1) + node];
    int end = g_rowptr[r * (N_NODES + 1) + node + 1];
    const int* col = g_col + (size_t)r * N_EDGES;
    for (int j = beg; j < end; ++j) {
        int src = col[j];
        float w = g_dinv[r * N_NODES + src];
        float4 sv = x4[(size_t)src * 32 + lane];
        acc.x += w * sv.x; acc.y += w * sv.y; acc.z += w * sv.z; acc.w += w * sv.w;
    }
    acc.x *= dd; acc.y *= dd; acc.z *= dd; acc.w *= dd;
    ((float4*)g_agg)[((size_t)r * N_NODES + node) * 32 + lane] = acc;
}

// ---------------- GEMM: C[M,128] = relu(A[M,K] @ B[K,128] + bias) ------------
// A element (n, kb) at A + (kb/128)*relStride + n*128 + (kb%128).
__global__ void __launch_bounds__(256) gemm_bias_relu(
    const float* __restrict__ A, size_t relStride, int K,
    const float* __restrict__ B, const float* __restrict__ bias, int nbias,
    float* __restrict__ C, int M, int doRelu)
{
    __shared__ float As[16][128];
    __shared__ float Bs[16][128];
    int tid = threadIdx.x;
    int rowBase = blockIdx.x * 128;
    int ty = tid >> 4;     // 0..15
    int tx = tid & 15;     // 0..15
    float acc[8][8];
    #pragma unroll
    for (int i = 0; i < 8; i++)
        #pragma unroll
        for (int j = 0; j < 8; j++) acc[i][j] = 0.f;

    int nkt = K >> 4;
    for (int kt = 0; kt < nkt; ++kt) {
        const float* Ag = A + (size_t)(kt >> 3) * relStride + ((kt & 7) << 4);
        const float* Bg = B + (size_t)kt * 16 * 128;
        #pragma unroll
        for (int p = 0; p < 2; p++) {
            int idx = tid + (p << 8);
            // A: 128 rows x 16 cols
            int m  = idx >> 2;
            int c4 = (idx & 3) << 2;
            int grow = rowBase + m;
            float4 v = make_float4(0.f, 0.f, 0.f, 0.f);
            if (grow < M) v = *(const float4*)(Ag + (size_t)grow * 128 + c4);
            As[c4 + 0][m] = v.x; As[c4 + 1][m] = v.y;
            As[c4 + 2][m] = v.z; As[c4 + 3][m] = v.w;
            // B: 16 rows x 128 cols
            int k  = idx >> 5;
            int n4 = (idx & 31) << 2;
            float4 w = *(const float4*)(Bg + (size_t)k * 128 + n4);
            *(float4*)&Bs[k][n4] = w;
        }
        __syncthreads();
        #pragma unroll
        for (int kk = 0; kk < 16; ++kk) {
            float a[8], bb[8];
            #pragma unroll
            for (int i = 0; i < 8; i++) a[i] = As[kk][ty * 8 + i];
            #pragma unroll
            for (int j = 0; j < 8; j++) bb[j] = Bs[kk][tx * 8 + j];
            #pragma unroll
            for (int i = 0; i < 8; i++)
                #pragma unroll
                for (int j = 0; j < 8; j++)
                    acc[i][j] += a[i] * bb[j];
        }
        __syncthreads();
    }

    float bcol[8];
    #pragma unroll
    for (int j = 0; j < 8; j++) {
        float s = 0.f;
        for (int r = 0; r < nbias; r++) s += bias[r * 128 + tx * 8 + j];
        bcol[j] = s;
    }
    #pragma unroll
    for (int i = 0; i < 8; i++) {
        int grow = rowBase + ty * 8 + i;
        if (grow < M) {
            float4 o0, o1;
            float v0 = acc[i][0] + bcol[0], v1 = acc[i][1] + bcol[1];
            float v2 = acc[i][2] + bcol[2], v3 = acc[i][3] + bcol[3];
            float v4 = acc[i][4] + bcol[4], v5 = acc[i][5] + bcol[5];
            float v6 = acc[i][6] + bcol[6], v7 = acc[i][7] + bcol[7];
            if (doRelu) {
                v0 = fmaxf(v0, 0.f); v1 = fmaxf(v1, 0.f); v2 = fmaxf(v2, 0.f); v3 = fmaxf(v3, 0.f);
                v4 = fmaxf(v4, 0.f); v5 = fmaxf(v5, 0.f); v6 = fmaxf(v6, 0.f); v7 = fmaxf(v7, 0.f);
            }
            o0 = make_float4(v0, v1, v2, v3);
            o1 = make_float4(v4, v5, v6, v7);
            *(float4*)(C + (size_t)grow * 128 + tx * 8)     = o0;
            *(float4*)(C + (size_t)grow * 128 + tx * 8 + 4) = o1;
        }
    }
}

// ---------------- BN column stats --------------------------------------------
__global__ void bn_stats_kernel(const float* __restrict__ H) {
    int f = threadIdx.x;   // 128 threads
    float s = 0.f, ss = 0.f;
    for (int n = blockIdx.x; n < N_NODES; n += gridDim.x) {
        float v = H[(size_t)n * 128 + f];
        s += v; ss += v * v;
    }
    atomicAdd(&g_bnsum[f], s);
    atomicAdd(&g_bnsq[f], ss);
}

// ---------------- fold BN into lin1 ------------------------------------------
__global__ void bn_fold_kernel(const float* __restrict__ gamma,
                               const float* __restrict__ beta,
                               const float* __restrict__ lin1W,
                               const float* __restrict__ lin1b)
{
    __shared__ float s_sc[128], s_sh[128];
    int j = threadIdx.x;
    float mean = g_bnsum[j] / (float)N_NODES;
    float var  = g_bnsq[j] / (float)N_NODES - mean * mean;
    float sc = gamma[j] * rsqrtf(var + BN_EPS);
    s_sc[j] = sc;
    s_sh[j] = beta[j] - mean * sc;
    __syncthreads();
    float bp = lin1b[j];
    for (int k = 0; k < 128; k++) {
        float w = lin1W[k * 128 + j];
        g_Wp[k * 128 + j] = s_sc[k] * w;
        bp += s_sh[k] * w;
    }
    g_bp[j] = bp;
}

// ---------------- lin2: out[n,0:2] = h3[n] @ W[128,2] + b --------------------
__global__ void lin2_kernel(const float* __restrict__ H3,
                            const float* __restrict__ W,
                            const float* __restrict__ b,
                            float* __restrict__ out)
{
    int warp = (blockIdx.x * blockDim.x + threadIdx.x) >> 5;
    int lane = threadIdx.x & 31;
    if (warp >= N_NODES) return;
    float4 h = ((const float4*)H3)[(size_t)warp * 32 + lane];
    int k = lane * 4;
    float a0 = h.x * W[(k + 0) * 2 + 0] + h.y * W[(k + 1) * 2 + 0]
             + h.z * W[(k + 2) * 2 + 0] + h.w * W[(k + 3) * 2 + 0];
    float a1 = h.x * W[(k + 0) * 2 + 1] + h.y * W[(k + 1) * 2 + 1]
             + h.z * W[(k + 2) * 2 + 1] + h.w * W[(k + 3) * 2 + 1];
    #pragma unroll
    for (int o = 16; o; o >>= 1) {
        a0 += __shfl_xor_sync(0xFFFFFFFFu, a0, o);
        a1 += __shfl_xor_sync(0xFFFFFFFFu, a1, o);
    }
    if (lane == 0) {
        out[(size_t)warp * 2 + 0] = a0 + b[0];
        out[(size_t)warp * 2 + 1] = a1 + b[1];
    }
}

// ---------------- launch ------------------------------------------------------
extern "C" void kernel_launch(void* const* d_in, const int* in_sizes, int n_in,
                              void* d_out, int out_size)
{
    const float* x      = (const float*)d_in[0];
    const int*   ei     = (const int*)d_in[1];
    const float* W1     = (const float*)d_in[2];
    const float* b1     = (const float*)d_in[3];
    const float* W2     = (const float*)d_in[4];
    const float* b2     = (const float*)d_in[5];
    const float* gamma  = (const float*)d_in[6];
    const float* beta   = (const float*)d_in[7];
    const float* lin1W  = (const float*)d_in[8];
    const float* lin1b  = (const float*)d_in[9];
    const float* lin2W  = (const float*)d_in[10];
    const float* lin2b  = (const float*)d_in[11];
    float* out = (float*)d_out;

    float *agg, *h1, *h2, *h3, *Wp, *bp;
    cudaGetSymbolAddress((void**)&agg, g_agg);
    cudaGetSymbolAddress((void**)&h1,  g_h1);
    cudaGetSymbolAddress((void**)&h2,  g_h2);
    cudaGetSymbolAddress((void**)&h3,  g_h3);
    cudaGetSymbolAddress((void**)&Wp,  g_Wp);
    cudaGetSymbolAddress((void**)&bp,  g_bp);

    const int edgeBlocks = (N_EDGES + 255) / 256;        // 1954
    const int nodeRelBlocks = (NREL * N_NODES + 255) / 256; // 782
    const int aggBlocks = (N_NODES + 7) / 8;             // 6250
    const int gemmBlocks = (N_NODES + 127) / 128;        // 391

    init_kernel<<<nodeRelBlocks, 256>>>();
    count_kernel<<<dim3(edgeBlocks, NREL), 256>>>(ei);
    scan_kernel<<<NREL, 1024>>>();
    dinv_kernel<<<nodeRelBlocks, 256>>>();
    fill_kernel<<<dim3(edgeBlocks, NREL), 256>>>(ei);

    // layer 1
    aggregate_kernel<<<dim3(aggBlocks, NREL), 256>>>(x);
    gemm_bias_relu<<<gemmBlocks, 256>>>(agg, (size_t)N_NODES * HID, NREL * HID,
                                        W1, b1, NREL, h1, N_NODES, 1);
    // layer 2
    aggregate_kernel<<<dim3(aggBlocks, NREL), 256>>>(h1);
    gemm_bias_relu<<<gemmBlocks, 256>>>(agg, (size_t)N_NODES * HID, NREL * HID,
                                        W2, b2, NREL, h2, N_NODES, 1);
    // batchnorm folded into lin1
    bn_stats_kernel<<<512, 128>>>(h2);
    bn_fold_kernel<<<1, 128>>>(gamma, beta, lin1W, lin1b);
    gemm_bias_relu<<<gemmBlocks, 256>>>(h2, 0, HID, Wp, bp, 1, h3, N_NODES, 1);
    // lin2
    lin2_kernel<<<aggBlocks, 256>>>(h3, lin2W, lin2b, out);
}

// round 2
// speedup vs baseline: 1.0775x; 1.0775x over previous
#include <cuda_runtime.h>
#include <cstddef>

#define N_NODES 50000
#define N_EDGES 500000
#define HID 128
#define NREL 4
#define BN_EPS 1e-5f
#define NBLK 49   // ceil(50000/1024)

// ---------------- scratch (static device globals) ----------------------------
__device__ int   g_cnt[NREL * N_NODES];
__device__ int   g_cursor[NREL * N_NODES];
__device__ float g_dinv[NREL * N_NODES];
__device__ int   g_rowptr[NREL * (N_NODES + 1)];
__device__ int   g_col[NREL * N_EDGES];
__device__ int   g_bsum[NREL * 64];
__device__ int   g_boff[NREL * 64];
__device__ float g_agg[(size_t)NREL * N_NODES * HID];
__device__ float g_h1[(size_t)N_NODES * HID];
__device__ float g_h2[(size_t)N_NODES * HID];
__device__ float g_bnsum[HID];
__device__ float g_bnsq[HID];
__device__ float g_Wp[HID * HID];
__device__ float g_bp[HID];

// ---------------- f32x2 helpers ----------------------------------------------
__device__ __forceinline__ unsigned long long pk2(float lo, float hi) {
    unsigned long long r;
    asm("mov.b64 %0, {%1, %2};" : "=l"(r) : "f"(lo), "f"(hi));
    return r;
}
__device__ __forceinline__ void fma2(unsigned long long &d,
                                     unsigned long long a, unsigned long long b) {
    asm("fma.rn.f32x2 %0, %1, %2, %3;" : "=l"(d) : "l"(a), "l"(b), "l"(d));
}
__device__ __forceinline__ void up2(unsigned long long v, float &a, float &b) {
    asm("mov.b64 {%0, %1}, %2;" : "=f"(a), "=f"(b) : "l"(v));
}

// ---------------- degree count ------------------------------------------------
__global__ void count_kernel(const int* __restrict__ ei) {
    int r = blockIdx.y;
    int e = blockIdx.x * blockDim.x + threadIdx.x;
    if (e >= N_EDGES) return;
    int dst = ei[((size_t)r * 2 + 1) * N_EDGES + e];
    atomicAdd(&g_cnt[r * N_NODES + dst], 1);
}

// ---------------- dinv ---------------------------------------------------------
__global__ void dinv_kernel() {
    int i = blockIdx.x * blockDim.x + threadIdx.x;
    if (i >= NREL * N_NODES) return;
    g_dinv[i] = rsqrtf((float)g_cnt[i] + 1.0f);
}

// ---------------- 3-phase scan -------------------------------------------------
__global__ void scanA_kernel() {   // grid (NBLK, NREL), 1024 thr
    int r = blockIdx.y, blk = blockIdx.x, tid = threadIdx.x;
    __shared__ int s[1024];
    int i = blk * 1024 + tid;
    int v = (i < N_NODES) ? g_cnt[r * N_NODES + i] : 0;
    s[tid] = v;
    #pragma unroll
    for (int d = 1; d < 1024; d <<= 1) {
        __syncthreads();
        int t = (tid >= d) ? s[tid - d] : 0;
        __syncthreads();
        s[tid] += t;
    }
    __syncthreads();
    if (i < N_NODES) g_rowptr[r * (N_NODES + 1) + i + 1] = s[tid];
    if (tid == 1023) g_bsum[r * 64 + blk] = s[tid];
}

__global__ void scanB_kernel() {   // grid NREL, 64 thr
    int r = blockIdx.x, t = threadIdx.x;
    __shared__ int s[64];
    int v = (t < NBLK) ? g_bsum[r * 64 + t] : 0;
    s[t] = v;
    __syncthreads();
    #pragma unroll
    for (int d = 1; d < 64; d <<= 1) {
        int x = (t >= d) ? s[t - d] : 0;
        __syncthreads();
        s[t] += x;
        __syncthreads();
    }
    g_boff[r * 64 + t] = s[t] - v;
    if (t == 0) g_rowptr[r * (N_NODES + 1)] = 0;
}

__global__ void scanC_kernel() {   // grid (NBLK, NREL), 1024 thr
    int r = blockIdx.y;
    int i = blockIdx.x * 1024 + threadIdx.x;
    if (i < N_NODES)
        g_rowptr[r * (N_NODES + 1) + i + 1] += g_boff[r * 64 + blockIdx.x];
}

// ---------------- fill CSR -----------------------------------------------------
__global__ void fill_kernel(const int* __restrict__ ei) {
    int r = blockIdx.y;
    int e = blockIdx.x * blockDim.x + threadIdx.x;
    if (e >= N_EDGES) return;
    int src = ei[(size_t)r * 2 * N_EDGES + e];
    int dst = ei[((size_t)r * 2 + 1) * N_EDGES + e];
    int pos = g_rowptr[r * (N_NODES + 1) + dst] + atomicAdd(&g_cursor[r * N_NODES + dst], 1);
    g_col[(size_t)r * N_EDGES + pos] = src;
}

// ---------------- CSR aggregate ------------------------------------------------
__global__ void aggregate_kernel(const float* __restrict__ X) {
    int r = blockIdx.y;
    int node = blockIdx.x * 8 + (threadIdx.x >> 5);
    if (node >= N_NODES) return;
    int lane = threadIdx.x & 31;
    const float4* x4 = (const float4*)X;
    float dd = g_dinv[r * N_NODES + node];
    float4 xv = x4[(size_t)node * 32 + lane];
    float4 acc;
    acc.x = dd * xv.x; acc.y = dd * xv.y; acc.z = dd * xv.z; acc.w = dd * xv.w;
    int beg = g_rowptr[r * (N_NODES + 1) + node];
    int end = g_rowptr[r * (N_NODES + 1) + node + 1];
    const int* col = g_col + (size_t)r * N_EDGES;
    for (int j = beg; j < end; ++j) {
        int src = col[j];
        float w = g_dinv[r * N_NODES + src];
        float4 sv = x4[(size_t)src * 32 + lane];
        acc.x += w * sv.x; acc.y += w * sv.y; acc.z += w * sv.z; acc.w += w * sv.w;
    }
    acc.x *= dd; acc.y *= dd; acc.z *= dd; acc.w *= dd;
    ((float4*)g_agg)[((size_t)r * N_NODES + node) * 32 + lane] = acc;
}

// ---------------- GEMM with f32x2, prefetch, optional fused lin2 ---------------
// C[M,128] = relu(A[M,K] @ B[K,128] + bias). If out2 != null, instead emit
// out2[M,2] = relu(...) @ l2W + l2b (C not written).
__global__ void __launch_bounds__(256) gemm_fused(
    const float* __restrict__ A, size_t relStride, int K,
    const float* __restrict__ B, const float* __restrict__ bias, int nbias,
    float* __restrict__ C, int M, int doRelu,
    const float* __restrict__ l2W, const float* __restrict__ l2b,
    float* __restrict__ out2)
{
    __shared__ float As[16][128];
    __shared__ float Bs[16][128];
    int tid = threadIdx.x;
    int rowBase = blockIdx.x * 128;
    int ty = tid >> 4;
    int tx = tid & 15;

    unsigned long long acc2[8][4];
    #pragma unroll
    for (int i = 0; i < 8; i++)
        #pragma unroll
        for (int jj = 0; jj < 4; jj++) acc2[i][jj] = 0ULL;

    int nkt = K >> 4;
    float4 pA[2], pB[2];

    // prefetch tile 0
    {
        const float* Ag = A;
        const float* Bg = B;
        #pragma unroll
        for (int p = 0; p < 2; p++) {
            int idx = tid + (p << 8);
            int m = idx >> 2, c4 = (idx & 3) << 2;
            int grow = rowBase + m;
            pA[p] = make_float4(0.f, 0.f, 0.f, 0.f);
            if (grow < M) pA[p] = *(const float4*)(Ag + (size_t)grow * 128 + c4);
            int k = idx >> 5, n4 = (idx & 31) << 2;
            pB[p] = *(const float4*)(Bg + (size_t)k * 128 + n4);
        }
    }

    for (int kt = 0; kt < nkt; ++kt) {
        // commit prefetched tile to smem
        #pragma unroll
        for (int p = 0; p < 2; p++) {
            int idx = tid + (p << 8);
            int m = idx >> 2, c4 = (idx & 3) << 2;
            As[c4 + 0][m] = pA[p].x; As[c4 + 1][m] = pA[p].y;
            As[c4 + 2][m] = pA[p].z; As[c4 + 3][m] = pA[p].w;
            int k = idx >> 5, n4 = (idx & 31) << 2;
            *(float4*)&Bs[k][n4] = pB[p];
        }
        __syncthreads();

        // prefetch next tile
        if (kt + 1 < nkt) {
            int ktn = kt + 1;
            const float* Ag = A + (size_t)(ktn >> 3) * relStride + ((ktn & 7) << 4);
            const float* Bg = B + (size_t)ktn * 2048;
            #pragma unroll
            for (int p = 0; p < 2; p++) {
                int idx = tid + (p << 8);
                int m = idx >> 2, c4 = (idx & 3) << 2;
                int grow = rowBase + m;
                pA[p] = make_float4(0.f, 0.f, 0.f, 0.f);
                if (grow < M) pA[p] = *(const float4*)(Ag + (size_t)grow * 128 + c4);
                int k = idx >> 5, n4 = (idx & 31) << 2;
                pB[p] = *(const float4*)(Bg + (size_t)k * 128 + n4);
            }
        }

        // compute
        #pragma unroll
        for (int kk = 0; kk < 16; ++kk) {
            const float4* ap = (const float4*)&As[kk][ty * 8];
            float4 a0 = ap[0], a1 = ap[1];
            const ulonglong2* bp = (const ulonglong2*)&Bs[kk][tx * 8];
            ulonglong2 b01 = bp[0], b23 = bp[1];
            unsigned long long bb[4] = { b01.x, b01.y, b23.x, b23.y };
            float av[8] = { a0.x, a0.y, a0.z, a0.w, a1.x, a1.y, a1.z, a1.w };
            #pragma unroll
            for (int i = 0; i < 8; i++) {
                unsigned long long aa = pk2(av[i], av[i]);
                #pragma unroll
                for (int jj = 0; jj < 4; jj++)
                    fma2(acc2[i][jj], aa, bb[jj]);
            }
        }
        __syncthreads();
    }

    // bias (sum over relations)
    float bcol[8];
    #pragma unroll
    for (int j = 0; j < 8; j++) {
        float s = 0.f;
        for (int r = 0; r < nbias; r++) s += bias[r * 128 + tx * 8 + j];
        bcol[j] = s;
    }

    if (out2) {
        float w0[8], w1[8];
        #pragma unroll
        for (int j = 0; j < 8; j++) {
            w0[j] = l2W[(tx * 8 + j) * 2 + 0];
            w1[j] = l2W[(tx * 8 + j) * 2 + 1];
        }
        float l20 = l2b[0], l21 = l2b[1];
        #pragma unroll
        for (int i = 0; i < 8; i++) {
            float v[8];
            #pragma unroll
            for (int jj = 0; jj < 4; jj++) up2(acc2[i][jj], v[2 * jj], v[2 * jj + 1]);
            float p0 = 0.f, p1 = 0.f;
            #pragma unroll
            for (int j = 0; j < 8; j++) {
                float vv = v[j] + bcol[j];
                if (doRelu) vv = fmaxf(vv, 0.f);
                p0 += vv * w0[j];
                p1 += vv * w1[j];
            }
            #pragma unroll
            for (int o = 8; o; o >>= 1) {
                p0 += __shfl_xor_sync(0xFFFFFFFFu, p0, o);
                p1 += __shfl_xor_sync(0xFFFFFFFFu, p1, o);
            }
            int grow = rowBase + ty * 8 + i;
            if (tx == 0 && grow < M) {
                out2[(size_t)grow * 2 + 0] = p0 + l20;
                out2[(size_t)grow * 2 + 1] = p1 + l21;
            }
        }
    } else {
        #pragma unroll
        for (int i = 0; i < 8; i++) {
            int grow = rowBase + ty * 8 + i;
            if (grow < M) {
                float v[8];
                #pragma unroll
                for (int jj = 0; jj < 4; jj++) up2(acc2[i][jj], v[2 * jj], v[2 * jj + 1]);
                #pragma unroll
                for (int j = 0; j < 8; j++) {
                    v[j] += bcol[j];
                    if (doRelu) v[j] = fmaxf(v[j], 0.f);
                }
                *(float4*)(C + (size_t)grow * 128 + tx * 8)     = make_float4(v[0], v[1], v[2], v[3]);
                *(float4*)(C + (size_t)grow * 128 + tx * 8 + 4) = make_float4(v[4], v[5], v[6], v[7]);
            }
        }
    }
}

// ---------------- BN column stats ---------------------------------------------
__global__ void bn_stats_kernel(const float* __restrict__ H) {
    int f = threadIdx.x;
    float s = 0.f, ss = 0.f;
    for (int n = blockIdx.x; n < N_NODES; n += gridDim.x) {
        float v = H[(size_t)n * 128 + f];
        s += v; ss += v * v;
    }
    atomicAdd(&g_bnsum[f], s);
    atomicAdd(&g_bnsq[f], ss);
}

// ---------------- fold BN into lin1 -------------------------------------------
__global__ void bn_fold_kernel(const float* __restrict__ gamma,
                               const float* __restrict__ beta,
                               const float* __restrict__ lin1W,
                               const float* __restrict__ lin1b)
{
    __shared__ float s_sc[128], s_sh[128];
    int j = threadIdx.x;
    float mean = g_bnsum[j] / (float)N_NODES;
    float var  = g_bnsq[j] / (float)N_NODES - mean * mean;
    float sc = gamma[j] * rsqrtf(var + BN_EPS);
    s_sc[j] = sc;
    s_sh[j] = beta[j] - mean * sc;
    __syncthreads();
    float bp = lin1b[j];
    for (int k = 0; k < 128; k++) {
        float w = lin1W[k * 128 + j];
        g_Wp[k * 128 + j] = s_sc[k] * w;
        bp += s_sh[k] * w;
    }
    g_bp[j] = bp;
}

// ---------------- launch -------------------------------------------------------
extern "C" void kernel_launch(void* const* d_in, const int* in_sizes, int n_in,
                              void* d_out, int out_size)
{
    const float* x      = (const float*)d_in[0];
    const int*   ei     = (const int*)d_in[1];
    const float* W1     = (const float*)d_in[2];
    const float* b1     = (const float*)d_in[3];
    const float* W2     = (const float*)d_in[4];
    const float* b2     = (const float*)d_in[5];
    const float* gamma  = (const float*)d_in[6];
    const float* beta   = (const float*)d_in[7];
    const float* lin1W  = (const float*)d_in[8];
    const float* lin1b  = (const float*)d_in[9];
    const float* lin2W  = (const float*)d_in[10];
    const float* lin2b  = (const float*)d_in[11];
    float* out = (float*)d_out;

    float *agg, *h1, *h2, *Wp, *bp;
    int *cnt, *cursor;
    float *bnsum, *bnsq;
    cudaGetSymbolAddress((void**)&agg,    g_agg);
    cudaGetSymbolAddress((void**)&h1,     g_h1);
    cudaGetSymbolAddress((void**)&h2,     g_h2);
    cudaGetSymbolAddress((void**)&Wp,     g_Wp);
    cudaGetSymbolAddress((void**)&bp,     g_bp);
    cudaGetSymbolAddress((void**)&cnt,    g_cnt);
    cudaGetSymbolAddress((void**)&cursor, g_cursor);
    cudaGetSymbolAddress((void**)&bnsum,  g_bnsum);
    cudaGetSymbolAddress((void**)&bnsq,   g_bnsq);

    const int edgeBlocks = (N_EDGES + 255) / 256;
    const int nodeRelBlocks = (NREL * N_NODES + 255) / 256;
    const int aggBlocks = (N_NODES + 7) / 8;
    const int gemmBlocks = (N_NODES + 127) / 128;

    cudaMemsetAsync(cnt,    0, sizeof(int) * NREL * N_NODES);
    cudaMemsetAsync(cursor, 0, sizeof(int) * NREL * N_NODES);
    cudaMemsetAsync(bnsum,  0, sizeof(float) * HID);
    cudaMemsetAsync(bnsq,   0, sizeof(float) * HID);

    count_kernel<<<dim3(edgeBlocks, NREL), 256>>>(ei);
    scanA_kernel<<<dim3(NBLK, NREL), 1024>>>();
    scanB_kernel<<<NREL, 64>>>();
    scanC_kernel<<<dim3(NBLK, NREL), 1024>>>();
    dinv_kernel<<<nodeRelBlocks, 256>>>();
    fill_kernel<<<dim3(edgeBlocks, NREL), 256>>>(ei);

    // layer 1
    aggregate_kernel<<<dim3(aggBlocks, NREL), 256>>>(x);
    gemm_fused<<<gemmBlocks, 256>>>(agg, (size_t)N_NODES * HID, NREL * HID,
                                    W1, b1, NREL, h1, N_NODES, 1,
                                    nullptr, nullptr, nullptr);
    // layer 2
    aggregate_kernel<<<dim3(aggBlocks, NREL), 256>>>(h1);
    gemm_fused<<<gemmBlocks, 256>>>(agg, (size_t)N_NODES * HID, NREL * HID,
                                    W2, b2, NREL, h2, N_NODES, 1,
                                    nullptr, nullptr, nullptr);
    // batchnorm folded into lin1, lin2 fused into GEMM3 epilogue
    bn_stats_kernel<<<512, 128>>>(h2);
    bn_fold_kernel<<<1, 128>>>(gamma, beta, lin1W, lin1b);
    gemm_fused<<<gemmBlocks, 256>>>(h2, 0, HID, Wp, bp, 1,
                                    nullptr, N_NODES, 1,
                                    lin2W, lin2b, out);
}

// round 4
// speedup vs baseline: 1.7771x; 1.6493x over previous
#include <cuda_runtime.h>
#include <cuda_bf16.h>
#include <cstdint>
#include <cstddef>

#define N_NODES 50000
#define N_EDGES 500000
#define HID 128
#define NREL 4
#define BN_EPS 1e-5f
#define NBLK 49            // ceil(50000/1024)
#define MPAD 50048         // 391 * 128

// Feature gate: tcgen05 PTX only exists in the sm_103a pass. The plain
// compute_103 fallback PTX pass compiles dead no-op bodies instead.
#if defined(__CUDA_ARCH_FEAT_SM103_ALL)
#define HAS_TCGEN05 1
#else
#define HAS_TCGEN05 0
#endif

// ---------------- PTX helpers -------------------------------------------------
__device__ __forceinline__ uint32_t smem_to_u32(const void* p) {
    uint32_t a;
    asm("{ .reg .u64 t; cvta.to.shared.u64 t, %1; cvt.u32.u64 %0, t; }" : "=r"(a) : "l"(p));
    return a;
}
__device__ __forceinline__ uint32_t elect_one_pred() {
    uint32_t pred;
    asm volatile("{\n\t.reg .pred p;\n\telect.sync _|p, 0xFFFFFFFF;\n\tselp.b32 %0, 1, 0, p;\n\t}" : "=r"(pred));
    return pred;
}
#define MBARRIER_INIT(mbar, count) \
    asm volatile("mbarrier.init.shared.b64 [%0], %1;" :: "r"((uint32_t)(mbar)), "r"((uint32_t)(count)) : "memory")
#define MBARRIER_INVAL(mbar) \
    asm volatile("mbarrier.inval.shared.b64 [%0];" :: "r"((uint32_t)(mbar)) : "memory")
#define MBARRIER_WAIT_PARITY(mbar, parity) do { \
    uint32_t _m = (uint32_t)(mbar); uint32_t _p = (uint32_t)(parity); uint32_t _d; \
    asm volatile("{\n\t.reg .pred p;\n\tmbarrier.try_wait.parity.acquire.cta.shared::cta.b64 p, [%1], %2;\n\tselp.b32 %0, 1, 0, p;\n\t}" \
        : "=r"(_d) : "r"(_m), "r"(_p) : "memory"); \
    if (!_d) { \
        asm volatile("{\n\t.reg .pred P1;\n\tWL_%=:\n\tmbarrier.try_wait.parity.acquire.cta.shared::cta.b64 P1, [%0], %1, 0x989680;\n\t@P1 bra.uni WD_%=;\n\tbra.uni WL_%=;\n\tWD_%=:\n\t}" \
            :: "r"(_m), "r"(_p) : "memory"); \
    } \
} while (0)

#if HAS_TCGEN05
#define TCGEN05_ALLOC(smem_addr, nCols) \
    asm volatile("tcgen05.alloc.cta_group::1.sync.aligned.shared::cta.b32 [%0], %1;" \
        :: "r"((uint32_t)(smem_addr)), "r"((uint32_t)(nCols)) : "memory")
#define TCGEN05_DEALLOC(tmem, nCols) \
    asm volatile("tcgen05.dealloc.cta_group::1.sync.aligned.b32 %0, %1;" :: "r"(tmem), "r"((uint32_t)(nCols)))
#define TCGEN05_COMMIT(mbar) \
    asm volatile("tcgen05.commit.cta_group::1.mbarrier::arrive::one.shared::cluster.b64 [%0];" \
        :: "r"((uint32_t)(mbar)) : "memory")
#define TCGEN05_FENCE_AFTER() asm volatile("tcgen05.fence::after_thread_sync;" ::: "memory")
#define TCGEN05_WAIT_LD() asm volatile("tcgen05.wait::ld.sync.aligned;" ::: "memory")
#define TCGEN05_LD_X32(r, addr) \
    asm volatile("tcgen05.ld.sync.aligned.32x32b.x32.b32 " \
        "{%0, %1, %2, %3, %4, %5, %6, %7, %8, %9, %10, %11, %12, %13, %14, %15, " \
        "%16, %17, %18, %19, %20, %21, %22, %23, %24, %25, %26, %27, %28, %29, %30, %31}, [%32];" \
        : "=r"((r)[0]), "=r"((r)[1]), "=r"((r)[2]), "=r"((r)[3]), "=r"((r)[4]), "=r"((r)[5]), "=r"((r)[6]), "=r"((r)[7]), \
          "=r"((r)[8]), "=r"((r)[9]), "=r"((r)[10]), "=r"((r)[11]), "=r"((r)[12]), "=r"((r)[13]), "=r"((r)[14]), "=r"((r)[15]), \
          "=r"((r)[16]), "=r"((r)[17]), "=r"((r)[18]), "=r"((r)[19]), "=r"((r)[20]), "=r"((r)[21]), "=r"((r)[22]), "=r"((r)[23]), \
          "=r"((r)[24]), "=r"((r)[25]), "=r"((r)[26]), "=r"((r)[27]), "=r"((r)[28]), "=r"((r)[29]), "=r"((r)[30]), "=r"((r)[31]) \
        : "r"(addr))
__device__ __forceinline__ void mma_f16_ss(uint32_t d, uint64_t adesc, uint64_t bdesc,
                                           uint32_t idesc, uint32_t en) {
    asm volatile(
        "{\n\t.reg .pred p;\n\tsetp.ne.u32 p, %5, 0;\n\t"
        "tcgen05.mma.cta_group::1.kind::f16 [%0], %1, %2, %3, {%4, %4, %4, %4}, p;\n\t}"
        :: "r"(d), "l"(adesc), "l"(bdesc), "r"(idesc), "r"(0u), "r"(en) : "memory");
}
#else
#define TCGEN05_ALLOC(smem_addr, nCols)  do {} while (0)
#define TCGEN05_DEALLOC(tmem, nCols)     do {} while (0)
#define TCGEN05_COMMIT(mbar)             do {} while (0)
#define TCGEN05_FENCE_AFTER()            do {} while (0)
#define TCGEN05_WAIT_LD()                do {} while (0)
#define TCGEN05_LD_X32(r, addr) \
    do { _Pragma("unroll") for (int _i = 0; _i < 32; ++_i) (r)[_i] = 0u; (void)(addr); } while (0)
__device__ __forceinline__ void mma_f16_ss(uint32_t, uint64_t, uint64_t, uint32_t, uint32_t) {}
#endif

#define FENCE_PROXY_ASYNC() asm volatile("fence.proxy.async.shared::cta;" ::: "memory")

// desc: SW128, version=1, SBO=64, LBO=1 (K-major)
__device__ __forceinline__ uint64_t make_desc(uint32_t addr) {
    uint64_t d = (uint64_t(2) << 61) | (uint64_t(1) << 46) | (uint64_t(64) << 32) | (uint64_t(1) << 16);
    return d | ((uint64_t)(addr >> 4) & 0x3FFF);
}
// idesc: F32 acc, BF16xBF16, M=128, N=128
#define MMA_IDESC 0x8200490u

__device__ __forceinline__ unsigned bf16_us(__nv_bfloat16 h) { return (unsigned)__bfloat16_as_ushort(h); }

// ---------------- scratch -----------------------------------------------------
__device__ int   g_cnt[NREL * N_NODES];
__device__ int   g_cursor[NREL * N_NODES];
__device__ float g_dinv[NREL * N_NODES];
__device__ int   g_rowptr[NREL * (N_NODES + 1)];
__device__ int   g_col[NREL * N_EDGES];
__device__ int   g_bsum[NREL * 64];
__device__ int   g_boff[NREL * 64];
__device__ __nv_bfloat16 g_agghi[(size_t)NREL * MPAD * HID];
__device__ __nv_bfloat16 g_agglo[(size_t)NREL * MPAD * HID];
__device__ __nv_bfloat16 g_B1hi[NREL * HID * HID];
__device__ __nv_bfloat16 g_B1lo[NREL * HID * HID];
__device__ __nv_bfloat16 g_B2hi[NREL * HID * HID];
__device__ __nv_bfloat16 g_B2lo[NREL * HID * HID];
__device__ __nv_bfloat16 g_Wphi[HID * HID];
__device__ __nv_bfloat16 g_Wplo[HID * HID];
__device__ __nv_bfloat16 g_h2hi[(size_t)MPAD * HID];
__device__ __nv_bfloat16 g_h2lo[(size_t)MPAD * HID];
__device__ float g_h1[(size_t)N_NODES * HID];
__device__ float g_h2[(size_t)N_NODES * HID];
__device__ float g_bnsum[HID];
__device__ float g_bnsq[HID];
__device__ float g_Wp[HID * HID];
__device__ float g_bp[HID];

// ---------------- CSR build ---------------------------------------------------
__global__ void count_kernel(const int* __restrict__ ei) {
    int r = blockIdx.y;
    int e = blockIdx.x * blockDim.x + threadIdx.x;
    if (e >= N_EDGES) return;
    int dst = ei[((size_t)r * 2 + 1) * N_EDGES + e];
    atomicAdd(&g_cnt[r * N_NODES + dst], 1);
}

__global__ void scanA_kernel() {   // grid (NBLK, NREL), 1024 thr — also writes dinv
    int r = blockIdx.y, blk = blockIdx.x, tid = threadIdx.x;
    __shared__ int s[1024];
    int i = blk * 1024 + tid;
    int v0 = (i < N_NODES) ? g_cnt[r * N_NODES + i] : 0;
    s[tid] = v0;
    #pragma unroll
    for (int d = 1; d < 1024; d <<= 1) {
        __syncthreads();
        int t = (tid >= d) ? s[tid - d] : 0;
        __syncthreads();
        s[tid] += t;
    }
    __syncthreads();
    if (i < N_NODES) {
        g_rowptr[r * (N_NODES + 1) + i + 1] = s[tid];
        g_dinv[r * N_NODES + i] = rsqrtf((float)v0 + 1.0f);
    }
    if (tid == 1023) g_bsum[r * 64 + blk] = s[tid];
}

__global__ void scanB_kernel() {
    int r = blockIdx.x, t = threadIdx.x;
    __shared__ int s[64];
    int v = (t < NBLK) ? g_bsum[r * 64 + t] : 0;
    s[t] = v;
    __syncthreads();
    #pragma unroll
    for (int d = 1; d < 64; d <<= 1) {
        int x = (t >= d) ? s[t - d] : 0;
        __syncthreads();
        s[t] += x;
        __syncthreads();
    }
    g_boff[r * 64 + t] = s[t] - v;
    if (t == 0) g_rowptr[r * (N_NODES + 1)] = 0;
}

__global__ void scanC_kernel() {
    int r = blockIdx.y;
    int i = blockIdx.x * 1024 + threadIdx.x;
    if (i < N_NODES)
        g_rowptr[r * (N_NODES + 1) + i + 1] += g_boff[r * 64 + blockIdx.x];
}

__global__ void fill_kernel(const int* __restrict__ ei) {
    int r = blockIdx.y;
    int e = blockIdx.x * blockDim.x + threadIdx.x;
    if (e >= N_EDGES) return;
    int src = ei[(size_t)r * 2 * N_EDGES + e];
    int dst = ei[((size_t)r * 2 + 1) * N_EDGES + e];
    int pos = g_rowptr[r * (N_NODES + 1) + dst] + atomicAdd(&g_cursor[r * N_NODES + dst], 1);
    g_col[(size_t)r * N_EDGES + pos] = src;
}

// ---------------- weight prep: W[r][k][n] fp32 -> B[r][n][k] bf16 hi/lo --------
__global__ void bprep_kernel(const float* __restrict__ W1, const float* __restrict__ W2) {
    int i = blockIdx.x * blockDim.x + threadIdx.x;   // over NREL*128*128
    if (i >= NREL * HID * HID) return;
    int r = i >> 14, rem = i & 16383;
    int n = rem >> 7, k = rem & 127;
    size_t src = (size_t)r * 16384 + k * 128 + n;
    size_t dst = (size_t)r * 16384 + n * 128 + k;
    float v1 = W1[src];
    __nv_bfloat16 h1 = __float2bfloat16_rn(v1);
    g_B1hi[dst] = h1;
    g_B1lo[dst] = __float2bfloat16_rn(v1 - __bfloat162float(h1));
    float v2 = W2[src];
    __nv_bfloat16 h2 = __float2bfloat16_rn(v2);
    g_B2hi[dst] = h2;
    g_B2lo[dst] = __float2bfloat16_rn(v2 - __bfloat162float(h2));
}

__global__ void wpconv_kernel() {
    int i = blockIdx.x * blockDim.x + threadIdx.x;   // over 128*128
    if (i >= HID * HID) return;
    int n = i >> 7, k = i & 127;
    float v = g_Wp[k * 128 + n];
    __nv_bfloat16 h = __float2bfloat16_rn(v);
    g_Wphi[n * 128 + k] = h;
    g_Wplo[n * 128 + k] = __float2bfloat16_rn(v - __bfloat162float(h));
}

// ---------------- CSR aggregate -> bf16 hi/lo ---------------------------------
__global__ void aggregate_kernel(const float* __restrict__ X) {
    int r = blockIdx.y;
    int node = blockIdx.x * 8 + (threadIdx.x >> 5);
    if (node >= N_NODES) return;
    int lane = threadIdx.x & 31;
    const float4* x4 = (const float4*)X;
    float dd = g_dinv[r * N_NODES + node];
    float4 xv = x4[(size_t)node * 32 + lane];
    float4 acc;
    acc.x = dd * xv.x; acc.y = dd * xv.y; acc.z = dd * xv.z; acc.w = dd * xv.w;
    int beg = g_rowptr[r * (N_NODES + 1) + node];
    int end = g_rowptr[r * (N_NODES + 1) + node + 1];
    const int* col = g_col + (size_t)r * N_EDGES;
    for (int j = beg; j < end; ++j) {
        int src = col[j];
        float w = g_dinv[r * N_NODES + src];
        float4 sv = x4[(size_t)src * 32 + lane];
        acc.x += w * sv.x; acc.y += w * sv.y; acc.z += w * sv.z; acc.w += w * sv.w;
    }
    acc.x *= dd; acc.y *= dd; acc.z *= dd; acc.w *= dd;
    float v[4] = { acc.x, acc.y, acc.z, acc.w };
    unsigned hh[2], ll[2];
    #pragma unroll
    for (int p = 0; p < 2; p++) {
        __nv_bfloat16 h0 = __float2bfloat16_rn(v[2 * p]);
        __nv_bfloat16 h1 = __float2bfloat16_rn(v[2 * p + 1]);
        __nv_bfloat16 l0 = __float2bfloat16_rn(v[2 * p] - __bfloat162float(h0));
        __nv_bfloat16 l1 = __float2bfloat16_rn(v[2 * p + 1] - __bfloat162float(h1));
        hh[p] = bf16_us(h0) | (bf16_us(h1) << 16);
        ll[p] = bf16_us(l0) | (bf16_us(l1) << 16);
    }
    size_t base = ((size_t)r * MPAD + node) * 128 + 4 * lane;
    *(uint2*)(g_agghi + base) = make_uint2(hh[0], hh[1]);
    *(uint2*)(g_agglo + base) = make_uint2(ll[0], ll[1]);
}

// ---------------- tcgen05 split-bf16 GEMM -------------------------------------
// D[M,128] = sum_r A_r[M,128] @ B_r^T + bias; modes:
//   0: Hout = relu(D)
//   1: Hout = relu(D); also H2hi/H2lo = split(relu(D))
//   2: out2[M,2] = relu(D) @ l2W + l2b
#define SM_AHI 1024
#define SM_ALO (1024 + 32768)
#define SM_BHI (1024 + 65536)
#define SM_BLO (1024 + 98304)
#define SM_TOTAL (1024 + 131072)
#define SM_MBAR 8
#define SM_BIAS 16

__global__ void __launch_bounds__(256) mma_gemm(
    const __nv_bfloat16* __restrict__ Ahi, const __nv_bfloat16* __restrict__ Alo,
    const __nv_bfloat16* __restrict__ Bhi, const __nv_bfloat16* __restrict__ Blo,
    const float* __restrict__ bias, int nrel,
    float* __restrict__ Hout,
    __nv_bfloat16* __restrict__ H2hi, __nv_bfloat16* __restrict__ H2lo,
    const float* __restrict__ l2W, const float* __restrict__ l2b,
    float* __restrict__ out2, int mode)
{
    extern __shared__ char sm[];
    uint32_t smb = smem_to_u32(sm);
    int tid = threadIdx.x;
    int wid = tid >> 5;
    int rowBase = blockIdx.x * 128;

    if (wid == 0) TCGEN05_ALLOC(smb, 128);
    if (tid == 0) MBARRIER_INIT(smb + SM_MBAR, 1);
    if (tid < 128) {
        float s = 0.f;
        for (int r = 0; r < nrel; r++) s += bias[r * 128 + tid];
        *(float*)(sm + SM_BIAS + tid * 4) = s;
    }
    __syncthreads();
    uint32_t tmem;
    asm volatile("ld.shared.b32 %0, [%1];" : "=r"(tmem) : "r"(smb));

    for (int r = 0; r < nrel; ++r) {
        if (r) {
            MBARRIER_WAIT_PARITY(smb + SM_MBAR, (r - 1) & 1);
            __syncthreads();
        }
        // load A/B hi+lo tiles (blocked SW128 atom layout: 16 atom-rows x 2 atom-cols)
        for (int c = tid; c < 2048; c += 256) {
            int row = c >> 4;         // 0..127
            int kc  = c & 15;         // 16B chunk (8 bf16)
            uint32_t soff = (uint32_t)(((row >> 3) + ((kc >> 3) << 4)) * 1024 + (row & 7) * 128 + (kc & 7) * 16);
            soff = soff ^ ((soff >> 3) & 0x70);
            size_t gA = ((size_t)r * MPAD + rowBase + row) * 128 + kc * 8;
            *(uint4*)(sm + SM_AHI + soff) = *(const uint4*)(Ahi + gA);
            *(uint4*)(sm + SM_ALO + soff) = *(const uint4*)(Alo + gA);
            size_t gB = ((size_t)r * 128 + row) * 128 + kc * 8;
            *(uint4*)(sm + SM_BHI + soff) = *(const uint4*)(Bhi + gB);
            *(uint4*)(sm + SM_BLO + soff) = *(const uint4*)(Blo + gB);
        }
        __syncthreads();
        if (wid == 0) {
            FENCE_PROXY_ASYNC();
            if (elect_one_pred()) {
                uint64_t aH = make_desc(smb + SM_AHI);
                uint64_t aL = make_desc(smb + SM_ALO);
                uint64_t bH = make_desc(smb + SM_BHI);
                uint64_t bL = make_desc(smb + SM_BLO);
                #pragma unroll
                for (int s = 0; s < 8; ++s) {
                    uint64_t off = (uint64_t)((s >> 2) * 1024 + (s & 3) * 2);
                    mma_f16_ss(tmem, aH + off, bH + off, MMA_IDESC, !(r == 0 && s == 0));
                    mma_f16_ss(tmem, aH + off, bL + off, MMA_IDESC, 1u);
                    mma_f16_ss(tmem, aL + off, bH + off, MMA_IDESC, 1u);
                }
                TCGEN05_COMMIT(smb + SM_MBAR);
            }
        }
    }

    MBARRIER_WAIT_PARITY(smb + SM_MBAR, (nrel - 1) & 1);
    TCGEN05_FENCE_AFTER();

    if (tid < 128) {
        int row = rowBase + tid;
        float p0 = 0.f, p1 = 0.f;
        for (int ch = 0; ch < 4; ++ch) {
            uint32_t regs[32];
            TCGEN05_LD_X32(regs, tmem + ch * 32);
            TCGEN05_WAIT_LD();
            if (row < N_NODES) {
                float v[32];
                #pragma unroll
                for (int c = 0; c < 32; ++c) {
                    float b = *(const float*)(sm + SM_BIAS + (ch * 32 + c) * 4);
                    v[c] = fmaxf(__uint_as_float(regs[c]) + b, 0.f);
                }
                if (mode == 2) {
                    #pragma unroll
                    for (int c = 0; c < 32; ++c) {
                        int col = ch * 32 + c;
                        p0 += v[c] * l2W[col * 2 + 0];
                        p1 += v[c] * l2W[col * 2 + 1];
                    }
                } else {
                    #pragma unroll
                    for (int g = 0; g < 8; ++g)
                        *(float4*)(Hout + (size_t)row * 128 + ch * 32 + g * 4) =
                            make_float4(v[g * 4], v[g * 4 + 1], v[g * 4 + 2], v[g * 4 + 3]);
                    if (mode == 1) {
                        unsigned hh[16], ll[16];
                        #pragma unroll
                        for (int p = 0; p < 16; ++p) {
                            __nv_bfloat16 h0 = __float2bfloat16_rn(v[2 * p]);
                            __nv_bfloat16 h1 = __float2bfloat16_rn(v[2 * p + 1]);
                            __nv_bfloat16 l0 = __float2bfloat16_rn(v[2 * p] - __bfloat162float(h0));
                            __nv_bfloat16 l1 = __float2bfloat16_rn(v[2 * p + 1] - __bfloat162float(h1));
                            hh[p] = bf16_us(h0) | (bf16_us(h1) << 16);
                            ll[p] = bf16_us(l0) | (bf16_us(l1) << 16);
                        }
                        #pragma unroll
                        for (int g = 0; g < 4; ++g) {
                            *(uint4*)(H2hi + (size_t)row * 128 + ch * 32 + g * 8) =
                                make_uint4(hh[4 * g], hh[4 * g + 1], hh[4 * g + 2], hh[4 * g + 3]);
                            *(uint4*)(H2lo + (size_t)row * 128 + ch * 32 + g * 8) =
                                make_uint4(ll[4 * g], ll[4 * g + 1], ll[4 * g + 2], ll[4 * g + 3]);
                        }
                    }
                }
            }
        }
        if (mode == 2 && row < N_NODES) {
            out2[(size_t)row * 2 + 0] = p0 + l2b[0];
            out2[(size_t)row * 2 + 1] = p1 + l2b[1];
        }
    }
    __syncthreads();
    if (tid == 0) MBARRIER_INVAL(smb + SM_MBAR);
    if (wid == 0) TCGEN05_DEALLOC(tmem, 128);
}

// ---------------- BN ----------------------------------------------------------
__global__ void bn_stats_kernel(const float* __restrict__ H) {
    int f = threadIdx.x;
    float s = 0.f, ss = 0.f;
    for (int n = blockIdx.x; n < N_NODES; n += gridDim.x) {
        float v = H[(size_t)n * 128 + f];
        s += v; ss += v * v;
    }
    atomicAdd(&g_bnsum[f], s);
    atomicAdd(&g_bnsq[f], ss);
}

__global__ void bn_fold_kernel(const float* __restrict__ gamma,
                               const float* __restrict__ beta,
                               const float* __restrict__ lin1W,
                               const float* __restrict__ lin1b)
{
    __shared__ float s_sc[128], s_sh[128];
    int j = threadIdx.x;
    float mean = g_bnsum[j] / (float)N_NODES;
    float var  = g_bnsq[j] / (float)N_NODES - mean * mean;
    float sc = gamma[j] * rsqrtf(var + BN_EPS);
    s_sc[j] = sc;
    s_sh[j] = beta[j] - mean * sc;
    __syncthreads();
    float bp = lin1b[j];
    for (int k = 0; k < 128; k++) {
        float w = lin1W[k * 128 + j];
        g_Wp[k * 128 + j] = s_sc[k] * w;
        bp += s_sh[k] * w;
    }
    g_bp[j] = bp;
}

// ---------------- launch -------------------------------------------------------
extern "C" void kernel_launch(void* const* d_in, const int* in_sizes, int n_in,
                              void* d_out, int out_size)
{
    const float* x      = (const float*)d_in[0];
    const int*   ei     = (const int*)d_in[1];
    const float* W1     = (const float*)d_in[2];
    const float* b1     = (const float*)d_in[3];
    const float* W2     = (const float*)d_in[4];
    const float* b2     = (const float*)d_in[5];
    const float* gamma  = (const float*)d_in[6];
    const float* beta   = (const float*)d_in[7];
    const float* lin1W  = (const float*)d_in[8];
    const float* lin1b  = (const float*)d_in[9];
    const float* lin2W  = (const float*)d_in[10];
    const float* lin2b  = (const float*)d_in[11];
    float* out = (float*)d_out;

    cudaFuncSetAttribute(mma_gemm, cudaFuncAttributeMaxDynamicSharedMemorySize, SM_TOTAL);

    float *h1, *h2, *bp;
    int *cnt, *cursor;
    float *bnsum, *bnsq;
    __nv_bfloat16 *agghi, *agglo, *B1hi, *B1lo, *B2hi, *B2lo, *Wphi, *Wplo, *h2hi, *h2lo;
    cudaGetSymbolAddress((void**)&h1,     g_h1);
    cudaGetSymbolAddress((void**)&h2,     g_h2);
    cudaGetSymbolAddress((void**)&bp,     g_bp);
    cudaGetSymbolAddress((void**)&cnt,    g_cnt);
    cudaGetSymbolAddress((void**)&cursor, g_cursor);
    cudaGetSymbolAddress((void**)&bnsum,  g_bnsum);
    cudaGetSymbolAddress((void**)&bnsq,   g_bnsq);
    cudaGetSymbolAddress((void**)&agghi,  g_agghi);
    cudaGetSymbolAddress((void**)&agglo,  g_agglo);
    cudaGetSymbolAddress((void**)&B1hi,   g_B1hi);
    cudaGetSymbolAddress((void**)&B1lo,   g_B1lo);
    cudaGetSymbolAddress((void**)&B2hi,   g_B2hi);
    cudaGetSymbolAddress((void**)&B2lo,   g_B2lo);
    cudaGetSymbolAddress((void**)&Wphi,   g_Wphi);
    cudaGetSymbolAddress((void**)&Wplo,   g_Wplo);
    cudaGetSymbolAddress((void**)&h2hi,   g_h2hi);
    cudaGetSymbolAddress((void**)&h2lo,   g_h2lo);

    const int edgeBlocks = (N_EDGES + 255) / 256;
    const int aggBlocks  = (N_NODES + 7) / 8;
    const int gemmBlocks = MPAD / 128;   // 391

    cudaMemsetAsync(cnt,    0, sizeof(int) * NREL * N_NODES);
    cudaMemsetAsync(cursor, 0, sizeof(int) * NREL * N_NODES);
    cudaMemsetAsync(bnsum,  0, sizeof(float) * HID);
    cudaMemsetAsync(bnsq,   0, sizeof(float) * HID);

    bprep_kernel<<<(NREL * HID * HID + 255) / 256, 256>>>(W1, W2);
    count_kernel<<<dim3(edgeBlocks, NREL), 256>>>(ei);
    scanA_kernel<<<dim3(NBLK, NREL), 1024>>>();
    scanB_kernel<<<NREL, 64>>>();
    scanC_kernel<<<dim3(NBLK, NREL), 1024>>>();
    fill_kernel<<<dim3(edgeBlocks, NREL), 256>>>(ei);

    // layer 1
    aggregate_kernel<<<dim3(aggBlocks, NREL), 256>>>(x);
    mma_gemm<<<gemmBlocks, 256, SM_TOTAL>>>(agghi, agglo, B1hi, B1lo, b1, NREL,
                                            h1, nullptr, nullptr,
                                            nullptr, nullptr, nullptr, 0);
    // layer 2
    aggregate_kernel<<<dim3(aggBlocks, NREL), 256>>>(h1);
    mma_gemm<<<gemmBlocks, 256, SM_TOTAL>>>(agghi, agglo, B2hi, B2lo, b2, NREL,
                                            h2, h2hi, h2lo,
                                            nullptr, nullptr, nullptr, 1);
    // BN fold + lin1 + lin2
    bn_stats_kernel<<<512, 128>>>(h2);
    bn_fold_kernel<<<1, 128>>>(gamma, beta, lin1W, lin1b);
    wpconv_kernel<<<(HID * HID + 255) / 256, 256>>>();
    mma_gemm<<<gemmBlocks, 256, SM_TOTAL>>>(h2hi, h2lo, Wphi, Wplo, bp, 1,
                                            nullptr, nullptr, nullptr,
                                            lin2W, lin2b, out, 2);
}

// round 5
// speedup vs baseline: 1.8013x; 1.0136x over previous
#include <cuda_runtime.h>
#include <cuda_bf16.h>
#include <cstdint>
#include <cstddef>

#define N_NODES 50000
#define N_EDGES 500000
#define HID 128
#define NREL 4
#define BN_EPS 1e-5f
#define NBLK 49            // ceil(50000/1024)
#define MPAD 50048         // 391 * 128

#if defined(__CUDA_ARCH_FEAT_SM103_ALL)
#define HAS_TCGEN05 1
#else
#define HAS_TCGEN05 0
#endif

// ---------------- PTX helpers -------------------------------------------------
__device__ __forceinline__ uint32_t smem_to_u32(const void* p) {
    uint32_t a;
    asm("{ .reg .u64 t; cvta.to.shared.u64 t, %1; cvt.u32.u64 %0, t; }" : "=r"(a) : "l"(p));
    return a;
}
__device__ __forceinline__ uint32_t elect_one_pred() {
    uint32_t pred;
    asm volatile("{\n\t.reg .pred p;\n\telect.sync _|p, 0xFFFFFFFF;\n\tselp.b32 %0, 1, 0, p;\n\t}" : "=r"(pred));
    return pred;
}
#define MBARRIER_INIT(mbar, count) \
    asm volatile("mbarrier.init.shared.b64 [%0], %1;" :: "r"((uint32_t)(mbar)), "r"((uint32_t)(count)) : "memory")
#define MBARRIER_INVAL(mbar) \
    asm volatile("mbarrier.inval.shared.b64 [%0];" :: "r"((uint32_t)(mbar)) : "memory")
#define MBARRIER_WAIT_PARITY(mbar, parity) do { \
    uint32_t _m = (uint32_t)(mbar); uint32_t _p = (uint32_t)(parity); uint32_t _d; \
    asm volatile("{\n\t.reg .pred p;\n\tmbarrier.try_wait.parity.acquire.cta.shared::cta.b64 p, [%1], %2;\n\tselp.b32 %0, 1, 0, p;\n\t}" \
        : "=r"(_d) : "r"(_m), "r"(_p) : "memory"); \
    if (!_d) { \
        asm volatile("{\n\t.reg .pred P1;\n\tWL_%=:\n\tmbarrier.try_wait.parity.acquire.cta.shared::cta.b64 P1, [%0], %1, 0x989680;\n\t@P1 bra.uni WD_%=;\n\tbra.uni WL_%=;\n\tWD_%=:\n\t}" \
            :: "r"(_m), "r"(_p) : "memory"); \
    } \
} while (0)

#if HAS_TCGEN05
#define TCGEN05_ALLOC(smem_addr, nCols) \
    asm volatile("tcgen05.alloc.cta_group::1.sync.aligned.shared::cta.b32 [%0], %1;" \
        :: "r"((uint32_t)(smem_addr)), "r"((uint32_t)(nCols)) : "memory")
#define TCGEN05_DEALLOC(tmem, nCols) \
    asm volatile("tcgen05.dealloc.cta_group::1.sync.aligned.b32 %0, %1;" :: "r"(tmem), "r"((uint32_t)(nCols)))
#define TCGEN05_COMMIT(mbar) \
    asm volatile("tcgen05.commit.cta_group::1.mbarrier::arrive::one.shared::cluster.b64 [%0];" \
        :: "r"((uint32_t)(mbar)) : "memory")
#define TCGEN05_FENCE_AFTER() asm volatile("tcgen05.fence::after_thread_sync;" ::: "memory")
#define TCGEN05_WAIT_LD() asm volatile("tcgen05.wait::ld.sync.aligned;" ::: "memory")
#define TCGEN05_LD_X32(r, addr) \
    asm volatile("tcgen05.ld.sync.aligned.32x32b.x32.b32 " \
        "{%0, %1, %2, %3, %4, %5, %6, %7, %8, %9, %10, %11, %12, %13, %14, %15, " \
        "%16, %17, %18, %19, %20, %21, %22, %23, %24, %25, %26, %27, %28, %29, %30, %31}, [%32];" \
        : "=r"((r)[0]), "=r"((r)[1]), "=r"((r)[2]), "=r"((r)[3]), "=r"((r)[4]), "=r"((r)[5]), "=r"((r)[6]), "=r"((r)[7]), \
          "=r"((r)[8]), "=r"((r)[9]), "=r"((r)[10]), "=r"((r)[11]), "=r"((r)[12]), "=r"((r)[13]), "=r"((r)[14]), "=r"((r)[15]), \
          "=r"((r)[16]), "=r"((r)[17]), "=r"((r)[18]), "=r"((r)[19]), "=r"((r)[20]), "=r"((r)[21]), "=r"((r)[22]), "=r"((r)[23]), \
          "=r"((r)[24]), "=r"((r)[25]), "=r"((r)[26]), "=r"((r)[27]), "=r"((r)[28]), "=r"((r)[29]), "=r"((r)[30]), "=r"((r)[31]) \
        : "r"(addr))
__device__ __forceinline__ void mma_f16_ss(uint32_t d, uint64_t adesc, uint64_t bdesc,
                                           uint32_t idesc, uint32_t en) {
    asm volatile(
        "{\n\t.reg .pred p;\n\tsetp.ne.u32 p, %5, 0;\n\t"
        "tcgen05.mma.cta_group::1.kind::f16 [%0], %1, %2, %3, {%4, %4, %4, %4}, p;\n\t}"
        :: "r"(d), "l"(adesc), "l"(bdesc), "r"(idesc), "r"(0u), "r"(en) : "memory");
}
#else
#define TCGEN05_ALLOC(smem_addr, nCols)  do {} while (0)
#define TCGEN05_DEALLOC(tmem, nCols)     do {} while (0)
#define TCGEN05_COMMIT(mbar)             do {} while (0)
#define TCGEN05_FENCE_AFTER()            do {} while (0)
#define TCGEN05_WAIT_LD()                do {} while (0)
#define TCGEN05_LD_X32(r, addr) \
    do { _Pragma("unroll") for (int _i = 0; _i < 32; ++_i) (r)[_i] = 0u; (void)(addr); } while (0)
__device__ __forceinline__ void mma_f16_ss(uint32_t, uint64_t, uint64_t, uint32_t, uint32_t) {}
#endif

#define FENCE_PROXY_ASYNC() asm volatile("fence.proxy.async.shared::cta;" ::: "memory")

// desc: SW128, version=1, SBO=64, LBO=1 (K-major)
__device__ __forceinline__ uint64_t make_desc(uint32_t addr) {
    uint64_t d = (uint64_t(2) << 61) | (uint64_t(1) << 46) | (uint64_t(64) << 32) | (uint64_t(1) << 16);
    return d | ((uint64_t)(addr >> 4) & 0x3FFF);
}
// idesc: F32 acc, BF16xBF16, M=128, N=128
#define MMA_IDESC 0x8200490u

__device__ __forceinline__ unsigned bf16_us(__nv_bfloat16 h) { return (unsigned)__bfloat16_as_ushort(h); }

// ---------------- scratch -----------------------------------------------------
__device__ int   g_cnt[NREL * N_NODES];
__device__ int   g_cursor[NREL * N_NODES];
__device__ float g_dinv[NREL * N_NODES];
__device__ int   g_rowptr[NREL * (N_NODES + 1)];
__device__ int   g_col[NREL * N_EDGES];
__device__ int   g_bsum[NREL * 64];
__device__ int   g_boff[NREL * 64];
__device__ __nv_bfloat16 g_agghi[(size_t)NREL * MPAD * HID];
__device__ __nv_bfloat16 g_agglo[(size_t)NREL * MPAD * HID];
__device__ __nv_bfloat16 g_B1hi[NREL * HID * HID];
__device__ __nv_bfloat16 g_B1lo[NREL * HID * HID];
__device__ __nv_bfloat16 g_B2hi[NREL * HID * HID];
__device__ __nv_bfloat16 g_B2lo[NREL * HID * HID];
__device__ __nv_bfloat16 g_Wphi[HID * HID];
__device__ __nv_bfloat16 g_Wplo[HID * HID];
__device__ __nv_bfloat16 g_h2hi[(size_t)MPAD * HID];
__device__ __nv_bfloat16 g_h2lo[(size_t)MPAD * HID];
__device__ float g_h1[(size_t)N_NODES * HID];
__device__ float g_bnsum[HID];
__device__ float g_bnsq[HID];
__device__ float g_bp[HID];

// ---------------- CSR build ---------------------------------------------------
__global__ void count_kernel(const int* __restrict__ ei) {
    int r = blockIdx.y;
    int e = blockIdx.x * blockDim.x + threadIdx.x;
    if (e >= N_EDGES) return;
    int dst = ei[((size_t)r * 2 + 1) * N_EDGES + e];
    atomicAdd(&g_cnt[r * N_NODES + dst], 1);
}

__global__ void scanA_kernel() {   // grid (NBLK, NREL), 1024 thr — also writes dinv
    int r = blockIdx.y, blk = blockIdx.x, tid = threadIdx.x;
    __shared__ int s[1024];
    int i = blk * 1024 + tid;
    int v0 = (i < N_NODES) ? g_cnt[r * N_NODES + i] : 0;
    s[tid] = v0;
    #pragma unroll
    for (int d = 1; d < 1024; d <<= 1) {
        __syncthreads();
        int t = (tid >= d) ? s[tid - d] : 0;
        __syncthreads();
        s[tid] += t;
    }
    __syncthreads();
    if (i < N_NODES) {
        g_rowptr[r * (N_NODES + 1) + i + 1] = s[tid];
        g_dinv[r * N_NODES + i] = rsqrtf((float)v0 + 1.0f);
    }
    if (tid == 1023) g_bsum[r * 64 + blk] = s[tid];
}

__global__ void scanB_kernel() {
    int r = blockIdx.x, t = threadIdx.x;
    __shared__ int s[64];
    int v = (t < NBLK) ? g_bsum[r * 64 + t] : 0;
    s[t] = v;
    __syncthreads();
    #pragma unroll
    for (int d = 1; d < 64; d <<= 1) {
        int x = (t >= d) ? s[t - d] : 0;
        __syncthreads();
        s[t] += x;
        __syncthreads();
    }
    g_boff[r * 64 + t] = s[t] - v;
    if (t == 0) g_rowptr[r * (N_NODES + 1)] = 0;
}

__global__ void scanC_kernel() {
    int r = blockIdx.y;
    int i = blockIdx.x * 1024 + threadIdx.x;
    if (i < N_NODES)
        g_rowptr[r * (N_NODES + 1) + i + 1] += g_boff[r * 64 + blockIdx.x];
}

__global__ void fill_kernel(const int* __restrict__ ei) {
    int r = blockIdx.y;
    int e = blockIdx.x * blockDim.x + threadIdx.x;
    if (e >= N_EDGES) return;
    int src = ei[(size_t)r * 2 * N_EDGES + e];
    int dst = ei[((size_t)r * 2 + 1) * N_EDGES + e];
    int pos = g_rowptr[r * (N_NODES + 1) + dst] + atomicAdd(&g_cursor[r * N_NODES + dst], 1);
    g_col[(size_t)r * N_EDGES + pos] = src;
}

// ---------------- weight prep: W[r][k][n] fp32 -> B[r][n][k] bf16 hi/lo --------
__global__ void bprep_kernel(const float* __restrict__ W1, const float* __restrict__ W2) {
    int i = blockIdx.x * blockDim.x + threadIdx.x;
    if (i >= NREL * HID * HID) return;
    int r = i >> 14, rem = i & 16383;
    int n = rem >> 7, k = rem & 127;
    size_t src = (size_t)r * 16384 + k * 128 + n;
    size_t dst = (size_t)r * 16384 + n * 128 + k;
    float v1 = W1[src];
    __nv_bfloat16 h1 = __float2bfloat16_rn(v1);
    g_B1hi[dst] = h1;
    g_B1lo[dst] = __float2bfloat16_rn(v1 - __bfloat162float(h1));
    float v2 = W2[src];
    __nv_bfloat16 h2 = __float2bfloat16_rn(v2);
    g_B2hi[dst] = h2;
    g_B2lo[dst] = __float2bfloat16_rn(v2 - __bfloat162float(h2));
}

// ---------------- CSR aggregate (all relations per warp) -> bf16 hi/lo ---------
__global__ void aggregate_kernel(const float* __restrict__ X) {
    int node = blockIdx.x * 8 + (threadIdx.x >> 5);
    if (node >= N_NODES) return;
    int lane = threadIdx.x & 31;
    const float4* x4 = (const float4*)X;
    float4 xv = x4[(size_t)node * 32 + lane];

    #pragma unroll
    for (int r = 0; r < NREL; ++r) {
        const float* dinv = g_dinv + r * N_NODES;
        float dd = dinv[node];
        float4 acc;
        acc.x = dd * xv.x; acc.y = dd * xv.y; acc.z = dd * xv.z; acc.w = dd * xv.w;
        int beg = g_rowptr[r * (N_NODES + 1) + node];
        int end = g_rowptr[r * (N_NODES + 1) + node + 1];
        const int* col = g_col + (size_t)r * N_EDGES;
        int j = beg;
        for (; j + 2 <= end; j += 2) {
            int s0 = col[j], s1 = col[j + 1];
            float w0 = dinv[s0], w1 = dinv[s1];
            float4 v0 = x4[(size_t)s0 * 32 + lane];
            float4 v1 = x4[(size_t)s1 * 32 + lane];
            acc.x += w0 * v0.x + w1 * v1.x;
            acc.y += w0 * v0.y + w1 * v1.y;
            acc.z += w0 * v0.z + w1 * v1.z;
            acc.w += w0 * v0.w + w1 * v1.w;
        }
        if (j < end) {
            int s0 = col[j];
            float w0 = dinv[s0];
            float4 v0 = x4[(size_t)s0 * 32 + lane];
            acc.x += w0 * v0.x; acc.y += w0 * v0.y;
            acc.z += w0 * v0.z; acc.w += w0 * v0.w;
        }
        acc.x *= dd; acc.y *= dd; acc.z *= dd; acc.w *= dd;
        float v[4] = { acc.x, acc.y, acc.z, acc.w };
        unsigned hh[2], ll[2];
        #pragma unroll
        for (int p = 0; p < 2; p++) {
            __nv_bfloat16 h0 = __float2bfloat16_rn(v[2 * p]);
            __nv_bfloat16 h1 = __float2bfloat16_rn(v[2 * p + 1]);
            __nv_bfloat16 l0 = __float2bfloat16_rn(v[2 * p] - __bfloat162float(h0));
            __nv_bfloat16 l1 = __float2bfloat16_rn(v[2 * p + 1] - __bfloat162float(h1));
            hh[p] = bf16_us(h0) | (bf16_us(h1) << 16);
            ll[p] = bf16_us(l0) | (bf16_us(l1) << 16);
        }
        size_t base = ((size_t)r * MPAD + node) * 128 + 4 * lane;
        *(uint2*)(g_agghi + base) = make_uint2(hh[0], hh[1]);
        *(uint2*)(g_agglo + base) = make_uint2(ll[0], ll[1]);
    }
}

// ---------------- tcgen05 split-bf16 GEMM -------------------------------------
// D[M,128] = sum_r A_r[M,128] @ B_r^T + bias; modes:
//   0: Hout = relu(D)  (fp32, for next aggregate)
//   1: H2hi/H2lo = split(relu(D)); fused BN column stats into g_bnsum/g_bnsq
//   2: out2[M,2] = relu(D) @ l2W + l2b
#define SM_AHI 1024
#define SM_ALO (1024 + 32768)
#define SM_BHI (1024 + 65536)
#define SM_BLO (1024 + 98304)
#define SM_TOTAL (1024 + 131072)
#define SM_MBAR 8
#define SM_BIAS 16

__global__ void __launch_bounds__(256) mma_gemm(
    const __nv_bfloat16* __restrict__ Ahi, const __nv_bfloat16* __restrict__ Alo,
    const __nv_bfloat16* __restrict__ Bhi, const __nv_bfloat16* __restrict__ Blo,
    const float* __restrict__ bias, int nrel,
    float* __restrict__ Hout,
    __nv_bfloat16* __restrict__ H2hi, __nv_bfloat16* __restrict__ H2lo,
    const float* __restrict__ l2W, const float* __restrict__ l2b,
    float* __restrict__ out2, int mode)
{
    extern __shared__ char sm[];
    uint32_t smb = smem_to_u32(sm);
    int tid = threadIdx.x;
    int wid = tid >> 5;
    int rowBase = blockIdx.x * 128;

    if (wid == 0) TCGEN05_ALLOC(smb, 128);
    if (tid == 0) MBARRIER_INIT(smb + SM_MBAR, 1);
    if (tid < 128) {
        float s = 0.f;
        for (int r = 0; r < nrel; r++) s += bias[r * 128 + tid];
        *(float*)(sm + SM_BIAS + tid * 4) = s;
    }
    __syncthreads();
    uint32_t tmem;
    asm volatile("ld.shared.b32 %0, [%1];" : "=r"(tmem) : "r"(smb));

    for (int r = 0; r < nrel; ++r) {
        if (r) {
            MBARRIER_WAIT_PARITY(smb + SM_MBAR, (r - 1) & 1);
            __syncthreads();
        }
        // load A/B hi+lo tiles (blocked SW128 atom layout: 16 atom-rows x 2 atom-cols)
        for (int c = tid; c < 2048; c += 256) {
            int row = c >> 4;
            int kc  = c & 15;
            uint32_t soff = (uint32_t)(((row >> 3) + ((kc >> 3) << 4)) * 1024 + (row & 7) * 128 + (kc & 7) * 16);
            soff = soff ^ ((soff >> 3) & 0x70);
            size_t gA = ((size_t)r * MPAD + rowBase + row) * 128 + kc * 8;
            *(uint4*)(sm + SM_AHI + soff) = *(const uint4*)(Ahi + gA);
            *(uint4*)(sm + SM_ALO + soff) = *(const uint4*)(Alo + gA);
            size_t gB = ((size_t)r * 128 + row) * 128 + kc * 8;
            *(uint4*)(sm + SM_BHI + soff) = *(const uint4*)(Bhi + gB);
            *(uint4*)(sm + SM_BLO + soff) = *(const uint4*)(Blo + gB);
        }
        __syncthreads();
        if (wid == 0) {
            FENCE_PROXY_ASYNC();
            if (elect_one_pred()) {
                uint64_t aH = make_desc(smb + SM_AHI);
                uint64_t aL = make_desc(smb + SM_ALO);
                uint64_t bH = make_desc(smb + SM_BHI);
                uint64_t bL = make_desc(smb + SM_BLO);
                #pragma unroll
                for (int s = 0; s < 8; ++s) {
                    uint64_t off = (uint64_t)((s >> 2) * 1024 + (s & 3) * 2);
                    mma_f16_ss(tmem, aH + off, bH + off, MMA_IDESC, !(r == 0 && s == 0));
                    mma_f16_ss(tmem, aH + off, bL + off, MMA_IDESC, 1u);
                    mma_f16_ss(tmem, aL + off, bH + off, MMA_IDESC, 1u);
                }
                TCGEN05_COMMIT(smb + SM_MBAR);
            }
        }
    }

    MBARRIER_WAIT_PARITY(smb + SM_MBAR, (nrel - 1) & 1);
    TCGEN05_FENCE_AFTER();

    float* vs = (float*)(sm + SM_AHI);   // [128][129] scratch for BN stats (mode 1)

    if (tid < 128) {
        int row = rowBase + tid;
        bool active = row < N_NODES;
        float p0 = 0.f, p1 = 0.f;
        for (int ch = 0; ch < 4; ++ch) {
            uint32_t regs[32];
            TCGEN05_LD_X32(regs, tmem + ch * 32);
            TCGEN05_WAIT_LD();
            float v[32];
            #pragma unroll
            for (int c = 0; c < 32; ++c) {
                float b = *(const float*)(sm + SM_BIAS + (ch * 32 + c) * 4);
                v[c] = active ? fmaxf(__uint_as_float(regs[c]) + b, 0.f) : 0.f;
            }
            if (mode == 0) {
                if (active) {
                    #pragma unroll
                    for (int g = 0; g < 8; ++g)
                        *(float4*)(Hout + (size_t)row * 128 + ch * 32 + g * 4) =
                            make_float4(v[g * 4], v[g * 4 + 1], v[g * 4 + 2], v[g * 4 + 3]);
                }
            } else if (mode == 1) {
                #pragma unroll
                for (int c = 0; c < 32; ++c) vs[tid * 129 + ch * 32 + c] = v[c];
                if (active) {
                    unsigned hh[16], ll[16];
                    #pragma unroll
                    for (int p = 0; p < 16; ++p) {
                        __nv_bfloat16 h0 = __float2bfloat16_rn(v[2 * p]);
                        __nv_bfloat16 h1 = __float2bfloat16_rn(v[2 * p + 1]);
                        __nv_bfloat16 l0 = __float2bfloat16_rn(v[2 * p] - __bfloat162float(h0));
                        __nv_bfloat16 l1 = __float2bfloat16_rn(v[2 * p + 1] - __bfloat162float(h1));
                        hh[p] = bf16_us(h0) | (bf16_us(h1) << 16);
                        ll[p] = bf16_us(l0) | (bf16_us(l1) << 16);
                    }
                    #pragma unroll
                    for (int g = 0; g < 4; ++g) {
                        *(uint4*)(H2hi + (size_t)row * 128 + ch * 32 + g * 8) =
                            make_uint4(hh[4 * g], hh[4 * g + 1], hh[4 * g + 2], hh[4 * g + 3]);
                        *(uint4*)(H2lo + (size_t)row * 128 + ch * 32 + g * 8) =
                            make_uint4(ll[4 * g], ll[4 * g + 1], ll[4 * g + 2], ll[4 * g + 3]);
                    }
                }
            } else {   // mode 2
                #pragma unroll
                for (int c = 0; c < 32; ++c) {
                    int col = ch * 32 + c;
                    p0 += v[c] * l2W[col * 2 + 0];
                    p1 += v[c] * l2W[col * 2 + 1];
                }
            }
        }
        if (mode == 2 && active) {
            out2[(size_t)row * 2 + 0] = p0 + l2b[0];
            out2[(size_t)row * 2 + 1] = p1 + l2b[1];
        }
    }
    __syncthreads();

    if (mode == 1) {
        // column stats: thread t -> col t>>1, rows (t&1)*64 .. +64
        int col = tid >> 1;
        int r0 = (tid & 1) * 64;
        float s = 0.f, ss = 0.f;
        #pragma unroll 8
        for (int rr = 0; rr < 64; ++rr) {
            float v = vs[(r0 + rr) * 129 + col];
            s += v; ss += v * v;
        }
        atomicAdd(&g_bnsum[col], s);
        atomicAdd(&g_bnsq[col], ss);
        __syncthreads();
    }

    if (tid == 0) MBARRIER_INVAL(smb + SM_MBAR);
    if (wid == 0) TCGEN05_DEALLOC(tmem, 128);
}

// ---------------- fold BN into lin1, emit bf16 hi/lo directly ------------------
__global__ void bn_fold_kernel(const float* __restrict__ gamma,
                               const float* __restrict__ beta,
                               const float* __restrict__ lin1W,
                               const float* __restrict__ lin1b)
{
    __shared__ float s_sc[128], s_sh[128];
    int j = threadIdx.x;
    float mean = g_bnsum[j] / (float)N_NODES;
    float var  = g_bnsq[j] / (float)N_NODES - mean * mean;
    float sc = gamma[j] * rsqrtf(var + BN_EPS);
    s_sc[j] = sc;
    s_sh[j] = beta[j] - mean * sc;
    __syncthreads();
    float bp = lin1b[j];
    for (int k = 0; k < 128; k++) {
        float w = lin1W[k * 128 + j];
        float wp = s_sc[k] * w;
        __nv_bfloat16 h = __float2bfloat16_rn(wp);
        g_Wphi[j * 128 + k] = h;       // [n=j][k] layout for MMA B operand
        g_Wplo[j * 128 + k] = __float2bfloat16_rn(wp - __bfloat162float(h));
        bp += s_sh[k] * w;
    }
    g_bp[j] = bp;
}

// ---------------- launch -------------------------------------------------------
extern "C" void kernel_launch(void* const* d_in, const int* in_sizes, int n_in,
                              void* d_out, int out_size)
{
    const float* x      = (const float*)d_in[0];
    const int*   ei     = (const int*)d_in[1];
    const float* W1     = (const float*)d_in[2];
    const float* b1     = (const float*)d_in[3];
    const float* W2     = (const float*)d_in[4];
    const float* b2     = (const float*)d_in[5];
    const float* gamma  = (const float*)d_in[6];
    const float* beta   = (const float*)d_in[7];
    const float* lin1W  = (const float*)d_in[8];
    const float* lin1b  = (const float*)d_in[9];
    const float* lin2W  = (const float*)d_in[10];
    const float* lin2b  = (const float*)d_in[11];
    float* out = (float*)d_out;

    cudaFuncSetAttribute(mma_gemm, cudaFuncAttributeMaxDynamicSharedMemorySize, SM_TOTAL);

    float *h1, *bp;
    int *cnt, *cursor;
    float *bnsum, *bnsq;
    __nv_bfloat16 *agghi, *agglo, *B1hi, *B1lo, *B2hi, *B2lo, *Wphi, *Wplo, *h2hi, *h2lo;
    cudaGetSymbolAddress((void**)&h1,     g_h1);
    cudaGetSymbolAddress((void**)&bp,     g_bp);
    cudaGetSymbolAddress((void**)&cnt,    g_cnt);
    cudaGetSymbolAddress((void**)&cursor, g_cursor);
    cudaGetSymbolAddress((void**)&bnsum,  g_bnsum);
    cudaGetSymbolAddress((void**)&bnsq,   g_bnsq);
    cudaGetSymbolAddress((void**)&agghi,  g_agghi);
    cudaGetSymbolAddress((void**)&agglo,  g_agglo);
    cudaGetSymbolAddress((void**)&B1hi,   g_B1hi);
    cudaGetSymbolAddress((void**)&B1lo,   g_B1lo);
    cudaGetSymbolAddress((void**)&B2hi,   g_B2hi);
    cudaGetSymbolAddress((void**)&B2lo,   g_B2lo);
    cudaGetSymbolAddress((void**)&Wphi,   g_Wphi);
    cudaGetSymbolAddress((void**)&Wplo,   g_Wplo);
    cudaGetSymbolAddress((void**)&h2hi,   g_h2hi);
    cudaGetSymbolAddress((void**)&h2lo,   g_h2lo);

    const int edgeBlocks = (N_EDGES + 255) / 256;
    const int aggBlocks  = (N_NODES + 7) / 8;
    const int gemmBlocks = MPAD / 128;   // 391

    cudaMemsetAsync(cnt,    0, sizeof(int) * NREL * N_NODES);
    cudaMemsetAsync(cursor, 0, sizeof(int) * NREL * N_NODES);
    cudaMemsetAsync(bnsum,  0, sizeof(float) * HID);
    cudaMemsetAsync(bnsq,   0, sizeof(float) * HID);

    count_kernel<<<dim3(edgeBlocks, NREL), 256>>>(ei);
    scanA_kernel<<<dim3(NBLK, NREL), 1024>>>();
    scanB_kernel<<<NREL, 64>>>();
    scanC_kernel<<<dim3(NBLK, NREL), 1024>>>();
    fill_kernel<<<dim3(edgeBlocks, NREL), 256>>>(ei);

    // layer 1 (aggregate is kernel #6 so ncu -s 5 lands on it)
    aggregate_kernel<<<aggBlocks, 256>>>(x);
    bprep_kernel<<<(NREL * HID * HID + 255) / 256, 256>>>(W1, W2);
    mma_gemm<<<gemmBlocks, 256, SM_TOTAL>>>(agghi, agglo, B1hi, B1lo, b1, NREL,
                                            h1, nullptr, nullptr,
                                            nullptr, nullptr, nullptr, 0);
    // layer 2 (BN stats fused into epilogue)
    aggregate_kernel<<<aggBlocks, 256>>>(h1);
    mma_gemm<<<gemmBlocks, 256, SM_TOTAL>>>(agghi, agglo, B2hi, B2lo, b2, NREL,
                                            nullptr, h2hi, h2lo,
                                            nullptr, nullptr, nullptr, 1);
    // BN fold -> lin1 weights (bf16 hi/lo direct), then lin1+lin2 GEMM
    bn_fold_kernel<<<1, 128>>>(gamma, beta, lin1W, lin1b);
    mma_gemm<<<gemmBlocks, 256, SM_TOTAL>>>(h2hi, h2lo, Wphi, Wplo, bp, 1,
                                            nullptr, nullptr, nullptr,
                                            lin2W, lin2b, out, 2);
}